// round 11
// baseline (speedup 1.0000x reference)
#include <cuda_runtime.h>
#include <cuda_fp16.h>
#include <string.h>

#define N_MAX 50000
#define E_MAX 800000

// ---------------- scratch ----------------
__device__ __align__(16) float g_acc1[N_MAX * 8];    // per node: s1[3], deg, eagg[3], pad
__device__ __align__(16) __half2 g_aj2h[N_MAX * 32]; // aj2 in fp16 pairs (gather table)
__device__ __align__(16) float g_c2[N_MAX * 64];
__device__ __align__(16) float g_z3[N_MAX * 4];      // c3 @ Wc.T + bc
__device__ __align__(16) float g_y3[N_MAX * 4];      // aj3 @ Wc.T

// CSR
__device__ int  g_cnt[N_MAX];
__device__ int  g_off[N_MAX + 1];
__device__ int  g_cur[N_MAX];
__device__ unsigned long long g_desc[128];           // decoupled-lookback tile descriptors
__device__ int  g_csr[E_MAX];                        // src only, sorted by dst

// weights
__device__ float g_W1t[10 * 128];                    // rows: Wi(3), Wj(3), We(3), b
// pair-packed: float4 at [k2*64+o] = {Wi(2k2,o), Wj(2k2,o), Wi(2k2+1,o), Wj(2k2+1,o)}
__device__ __align__(16) float g_W2p[64 * 64 * 4];
__device__ float g_W2eb[4 * 64];                     // rows: We(3), b
__device__ __align__(16) float g_W3p[32 * 32 * 4];   // same pairing, k2<32, o<32
__device__ float g_W3eb[4 * 32];

__device__ __forceinline__ void fma2(unsigned long long& acc, unsigned long long h,
                                     unsigned long long w) {
    asm("fma.rn.f32x2 %0, %1, %2, %0;" : "+l"(acc) : "l"(h), "l"(w));
}

__device__ __forceinline__ unsigned long long packdup(float h) {
    float2 f = make_float2(h, h);
    unsigned long long u;
    memcpy(&u, &f, 8);
    return u;
}

// ---------------- weight prep + cnt/eagg/desc zero ----------------
__global__ void k_prep(const float* __restrict__ W1, const float* __restrict__ b1,
                       const float* __restrict__ W2, const float* __restrict__ b2,
                       const float* __restrict__ W3, const float* __restrict__ b3, int n) {
    int idx = blockIdx.x * blockDim.x + threadIdx.x;
    if (idx < 1280) {
        int k = idx / 128, o = idx % 128;
        g_W1t[idx] = (k < 9) ? W1[o * 9 + k] : b1[o];
        return;
    }
    idx -= 1280;
    if (idx < 16384) {                               // W2 pair-packed
        int c = idx & 3, o = (idx >> 2) & 63, k2 = idx >> 8;
        g_W2p[idx] = W2[o * 259 + (c & 1) * 128 + 2 * k2 + (c >> 1)];
        return;
    }
    idx -= 16384;
    if (idx < 256) {
        int k = idx / 64, o = idx % 64;
        g_W2eb[idx] = (k < 3) ? W2[o * 259 + 256 + k] : b2[o];
        return;
    }
    idx -= 256;
    if (idx < 4096) {                                // W3 pair-packed
        int c = idx & 3, o = (idx >> 2) & 31, k2 = idx >> 7;
        g_W3p[idx] = W3[o * 131 + (c & 1) * 64 + 2 * k2 + (c >> 1)];
        return;
    }
    idx -= 4096;
    if (idx < 128) {
        int k = idx / 32, o = idx % 32;
        g_W3eb[idx] = (k < 3) ? W3[o * 131 + 128 + k] : b3[o];
        return;
    }
    idx -= 128;
    if (idx < 128) {                                 // lookback descriptors
        g_desc[idx] = 0ull;
        return;
    }
    idx -= 128;
    if (idx < n) {
        g_cnt[idx] = 0;
        ((float4*)g_acc1)[idx * 2 + 1] = make_float4(0.f, 0.f, 0.f, 0.f);  // eagg
    }
}

// ---------------- CSR build ----------------
__global__ void k_count(const int* __restrict__ ei, int e, int half) {
    int t = blockIdx.x * blockDim.x + threadIdx.x;
    if (t >= half) return;
    int d0 = ei[e + t];
    int t2 = t + half;
    atomicAdd(&g_cnt[d0], 1);
    if (t2 < e) atomicAdd(&g_cnt[ei[e + t2]], 1);
}

// single-pass scan with decoupled lookback; writes g_off and g_cur
__global__ void k_scanall(int n) {
    __shared__ int ws[16];
    __shared__ int bprefix;
    int tid = threadIdx.x, lane = tid & 31, wid = tid >> 5;
    int tile = blockIdx.x;
    int i = tile * 512 + tid;
    int v = (i < n) ? g_cnt[i] : 0;
    int s = v;
#pragma unroll
    for (int of = 1; of < 32; of <<= 1) {
        int t = __shfl_up_sync(0xffffffffu, s, of);
        if (lane >= of) s += t;
    }
    if (lane == 31) ws[wid] = s;
    __syncthreads();
    if (wid == 0) {
        int vv = (lane < 16) ? ws[lane] : 0;
        int ss = vv;
#pragma unroll
        for (int of = 1; of < 16; of <<= 1) {
            int t = __shfl_up_sync(0xffffffffu, ss, of);
            if (lane >= of) ss += t;
        }
        if (lane < 16) ws[lane] = ss;
    }
    __syncthreads();
    if (wid) s += ws[wid - 1];
    int total = ws[15];

    if (tid == 0) {
        unsigned long long prefix = 0;
        if (tile == 0) {
            atomicExch(&g_desc[0], ((unsigned long long)total << 2) | 2ull);
        } else {
            atomicExch(&g_desc[tile], ((unsigned long long)total << 2) | 1ull);
            int tt = tile - 1;
            while (true) {
                unsigned long long d = atomicAdd(&g_desc[tt], 0ull);
                unsigned int st = (unsigned int)(d & 3ull);
                if (st == 2u) { prefix += d >> 2; break; }
                if (st == 1u) { prefix += d >> 2; tt--; }
            }
            atomicExch(&g_desc[tile],
                       ((prefix + (unsigned long long)total) << 2) | 2ull);
        }
        bprefix = (int)prefix;
    }
    __syncthreads();
    s += bprefix;
    if (i < n) {
        g_off[i + 1] = s;
        g_cur[i] = s - v;                            // start offset
    }
    if (i == 0) g_off[0] = 0;
}

// fill CSR (src only) + accumulate edge_attr into g_acc1; 2 edges/thread ILP
__global__ void k_fill(const int* __restrict__ ei, const float* __restrict__ ea,
                       int e, int half) {
    int t = blockIdx.x * blockDim.x + threadIdx.x;
    if (t >= half) return;
    int t2 = t + half;
    bool ok = t2 < e;
    int s0 = ei[t], d0 = ei[e + t];
    int s1 = 0, d1 = 0;
    if (ok) { s1 = ei[t2]; d1 = ei[e + t2]; }
    float e00 = ea[t * 3], e01 = ea[t * 3 + 1], e02 = ea[t * 3 + 2];
    float e10 = 0.f, e11 = 0.f, e12 = 0.f;
    if (ok) { e10 = ea[t2 * 3]; e11 = ea[t2 * 3 + 1]; e12 = ea[t2 * 3 + 2]; }
    int p0 = atomicAdd(&g_cur[d0], 1);
    int p1 = ok ? atomicAdd(&g_cur[d1], 1) : 0;
    g_csr[p0] = s0;
    if (ok) g_csr[p1] = s1;
    atomicAdd((float4*)&g_acc1[d0 * 8 + 4], make_float4(e00, e01, e02, 0.f));
    if (ok) atomicAdd((float4*)&g_acc1[d1 * 8 + 4], make_float4(e10, e11, e12, 0.f));
}

// ---------------- layer-1 aggregation (x gather only) ----------------
__global__ void k_agg1(const float* __restrict__ x, int n) {
    int i = blockIdx.x * blockDim.x + threadIdx.x;
    if (i >= n) return;
    int beg = g_off[i], end = g_off[i + 1];
    float a0 = x[i * 3], a1 = x[i * 3 + 1], a2 = x[i * 3 + 2];   // self loop
    float b0 = 0.f, b1 = 0.f, b2 = 0.f;
    float c0 = 0.f, c1 = 0.f, c2 = 0.f;
    float d0 = 0.f, d1 = 0.f, d2 = 0.f;
    int j = beg;
    for (; j + 4 <= end; j += 4) {
        int s0 = g_csr[j], s1 = g_csr[j + 1], s2 = g_csr[j + 2], s3 = g_csr[j + 3];
        a0 += x[s0 * 3]; a1 += x[s0 * 3 + 1]; a2 += x[s0 * 3 + 2];
        b0 += x[s1 * 3]; b1 += x[s1 * 3 + 1]; b2 += x[s1 * 3 + 2];
        c0 += x[s2 * 3]; c1 += x[s2 * 3 + 1]; c2 += x[s2 * 3 + 2];
        d0 += x[s3 * 3]; d1 += x[s3 * 3 + 1]; d2 += x[s3 * 3 + 2];
    }
    for (; j < end; j++) {
        int s0 = g_csr[j];
        a0 += x[s0 * 3]; a1 += x[s0 * 3 + 1]; a2 += x[s0 * 3 + 2];
    }
    ((float4*)g_acc1)[i * 2] = make_float4(a0 + b0 + c0 + d0, a1 + b1 + c1 + d1,
                                           a2 + b2 + c2 + d2, (float)(end - beg + 1));
}

// ---------------- fused layer1 + layer2 transform, blocked GEMM ----------------
__global__ void __launch_bounds__(128) k_l12(const float* __restrict__ x, int n) {
    __shared__ float mm[8][8];
    __shared__ float sxs[8][3];
    __shared__ __align__(16) float2 hs[8][128];      // (h,h) packed
    __shared__ __align__(16) float2 ps[4][8][64];    // per-warp partial (ai,aj)
    int t = threadIdx.x;
    int base = blockIdx.x * 8;

    if (t < 64) {
        int nd = t >> 3, c = t & 7;
        if (base + nd < n) mm[nd][c] = g_acc1[(base + nd) * 8 + c];
    } else if (t < 88) {
        int q = t - 64, nd = q / 3, c = q % 3;
        if (base + nd < n) sxs[nd][c] = x[(base + nd) * 3 + c];
    }
    __syncthreads();

    // phase A: h1 for 8 nodes
    {
        int nd = t >> 4, r = t & 15;
        bool ok = (base + nd < n);
#pragma unroll
        for (int p = 0; p < 8; p++) {
            int oo = r + p * 16;
            float h = 0.f;
            if (ok) {
                float ai = g_W1t[9 * 128 + oo]
                         + sxs[nd][0] * g_W1t[oo] + sxs[nd][1] * g_W1t[128 + oo]
                         + sxs[nd][2] * g_W1t[256 + oo];
                float rr = mm[nd][3] * ai
                         + mm[nd][0] * g_W1t[384 + oo] + mm[nd][1] * g_W1t[512 + oo]
                         + mm[nd][2] * g_W1t[640 + oo]
                         + mm[nd][4] * g_W1t[768 + oo] + mm[nd][5] * g_W1t[896 + oo]
                         + mm[nd][6] * g_W1t[1024 + oo];
                h = fmaxf(rr, 0.0f);
            }
            hs[nd][oo] = make_float2(h, h);
        }
    }
    __syncthreads();

    // phase B: k-split GEMM
    {
        int w = t >> 5, lane = t & 31;
        unsigned long long a0[8], a1[8];
#pragma unroll
        for (int nd = 0; nd < 8; nd++) { a0[nd] = 0ull; a1[nd] = 0ull; }
        const ulonglong2* Wp = (const ulonglong2*)g_W2p;
        const unsigned long long* hsu = (const unsigned long long*)hs;
        int k2b = w * 16;
#pragma unroll 4
        for (int kk = 0; kk < 16; kk++) {
            int k2 = k2b + kk;
            ulonglong2 wa = Wp[k2 * 64 + lane];
            ulonglong2 wb = Wp[k2 * 64 + 32 + lane];
#pragma unroll
            for (int nd = 0; nd < 8; nd++) {
                unsigned long long hp0 = hsu[nd * 128 + 2 * k2];
                unsigned long long hp1 = hsu[nd * 128 + 2 * k2 + 1];
                fma2(a0[nd], hp0, wa.x);
                fma2(a0[nd], hp1, wa.y);
                fma2(a1[nd], hp0, wb.x);
                fma2(a1[nd], hp1, wb.y);
            }
        }
        unsigned long long* psu = (unsigned long long*)ps;
#pragma unroll
        for (int nd = 0; nd < 8; nd++) {
            psu[(w * 8 + nd) * 64 + lane]      = a0[nd];
            psu[(w * 8 + nd) * 64 + lane + 32] = a1[nd];
        }
    }
    __syncthreads();

    // reduce 4 warp-partials per feature-pair, add c-terms, write c2 (f32) + aj2 (fp16x2)
    const float2* psf = (const float2*)ps;
#pragma unroll
    for (int q = 0; q < 2; q++) {
        int pi = t + 128 * q;                        // 0..255
        int nd = pi >> 5, o2 = pi & 31;              // node, feature pair
        int i = base + nd;
        if (i >= n) continue;
        int o = 2 * o2;
        float ai0 = 0.f, aj0 = 0.f, ai1 = 0.f, aj1 = 0.f;
#pragma unroll
        for (int w4 = 0; w4 < 4; w4++) {
            float2 pA = psf[(w4 * 8 + nd) * 64 + o];
            float2 pB = psf[(w4 * 8 + nd) * 64 + o + 1];
            ai0 += pA.x; aj0 += pA.y;
            ai1 += pB.x; aj1 += pB.y;
        }
        float deg = mm[nd][3];
        float c0 = deg * (ai0 + g_W2eb[192 + o]) + aj0
                 + mm[nd][4] * g_W2eb[o] + mm[nd][5] * g_W2eb[64 + o]
                 + mm[nd][6] * g_W2eb[128 + o];
        float c1 = deg * (ai1 + g_W2eb[192 + o + 1]) + aj1
                 + mm[nd][4] * g_W2eb[o + 1] + mm[nd][5] * g_W2eb[64 + o + 1]
                 + mm[nd][6] * g_W2eb[128 + o + 1];
        ((float2*)g_c2)[i * 32 + o2] = make_float2(c0, c1);
        g_aj2h[i * 32 + o2] = __floats2half2_rn(aj0, aj1);
    }
}

// ---------- fused layer2 agg + layer3 transform + classifier projection ----------
__global__ void __launch_bounds__(256) k_l23(const float* __restrict__ Wc,
                                             const float* __restrict__ bc, int n) {
    __shared__ float mm[16][8];
    __shared__ int offs[17];
    __shared__ __align__(16) unsigned long long hsu[16 * 64];   // (h,h) per column, 8KB
    __shared__ __align__(16) unsigned long long ps[8][16][32];  // per-warp partials, 32KB
    __shared__ float c3s[16][33];
    __shared__ float aj3s[16][33];
    __shared__ float wcs[128];
    __shared__ float bcs[4];
    int t = threadIdx.x;
    int base = blockIdx.x * 16;
    int w = t >> 5, lane = t & 31;

    if (t < 128) {
        int nd = t >> 3, c = t & 7;
        int i = base + nd;
        mm[nd][c] = (i < n) ? g_acc1[i * 8 + c] : 0.f;
    } else {
        wcs[t - 128] = Wc[t - 128];
    }
    if (t < 17) offs[t] = g_off[min(base + t, n)];
    if (t >= 20 && t < 24) bcs[t - 20] = bc[t - 20];
    __syncthreads();

    // gather phase: each warp handles nodes (w) and (w+8); fp16 rows, fp32 accumulate
    const float2* c2p = (const float2*)g_c2;
#pragma unroll
    for (int rep = 0; rep < 2; rep++) {
        int nd = w + rep * 8;
        int i = base + nd;
        if (i < n) {
            float2 acc = c2p[i * 32 + lane];
            float2 a1 = make_float2(0.f, 0.f), a2 = make_float2(0.f, 0.f),
                   a3 = make_float2(0.f, 0.f);
            int beg = offs[nd], end = offs[nd + 1];
            int j = beg;
            for (; j + 4 <= end; j += 4) {
                int s0 = g_csr[j], s1 = g_csr[j + 1];
                int s2 = g_csr[j + 2], s3 = g_csr[j + 3];
                float2 v0 = __half22float2(g_aj2h[s0 * 32 + lane]);
                float2 v1 = __half22float2(g_aj2h[s1 * 32 + lane]);
                float2 v2 = __half22float2(g_aj2h[s2 * 32 + lane]);
                float2 v3 = __half22float2(g_aj2h[s3 * 32 + lane]);
                acc.x += v0.x; acc.y += v0.y;
                a1.x += v1.x;  a1.y += v1.y;
                a2.x += v2.x;  a2.y += v2.y;
                a3.x += v3.x;  a3.y += v3.y;
            }
            for (; j < end; j++) {
                float2 v = __half22float2(g_aj2h[g_csr[j] * 32 + lane]);
                acc.x += v.x; acc.y += v.y;
            }
            float h0 = fmaxf(acc.x + a1.x + a2.x + a3.x, 0.0f);
            float h1 = fmaxf(acc.y + a1.y + a2.y + a3.y, 0.0f);
            hsu[nd * 64 + 2 * lane]     = packdup(h0);
            hsu[nd * 64 + 2 * lane + 1] = packdup(h1);
        } else {
            hsu[nd * 64 + 2 * lane]     = 0ull;
            hsu[nd * 64 + 2 * lane + 1] = 0ull;
        }
    }
    __syncthreads();

    // transform: 8 warps split k2 (4 each), 16 nodes, pair-packed (ai,aj)
    {
        unsigned long long acc[16];
#pragma unroll
        for (int nd = 0; nd < 16; nd++) acc[nd] = 0ull;
        const ulonglong2* Wp = (const ulonglong2*)g_W3p;
        int k2b = w * 4;
#pragma unroll
        for (int kk = 0; kk < 4; kk++) {
            int k2 = k2b + kk;
            ulonglong2 wv = Wp[k2 * 32 + lane];
#pragma unroll
            for (int nd = 0; nd < 16; nd++) {
                fma2(acc[nd], hsu[nd * 64 + 2 * k2], wv.x);
                fma2(acc[nd], hsu[nd * 64 + 2 * k2 + 1], wv.y);
            }
        }
#pragma unroll
        for (int nd = 0; nd < 16; nd++) ps[w][nd][lane] = acc[nd];
    }
    __syncthreads();

    // reduce 8 partials, apply c-terms -> c3s / aj3s in smem
#pragma unroll
    for (int rep = 0; rep < 2; rep++) {
        int pi = t + rep * 256;
        int nd = pi >> 5, o = pi & 31;
        int i = base + nd;
        if (i >= n) continue;
        float ai = 0.f, aj = 0.f;
#pragma unroll
        for (int w8 = 0; w8 < 8; w8++) {
            float2 p = *(const float2*)&ps[w8][nd][o];
            ai += p.x; aj += p.y;
        }
        float deg = mm[nd][3];
        float c = deg * (ai + g_W3eb[96 + o]) + aj;
        c += mm[nd][4] * g_W3eb[o] + mm[nd][5] * g_W3eb[32 + o] + mm[nd][6] * g_W3eb[64 + o];
        c3s[nd][o] = c;
        aj3s[nd][o] = aj;
    }
    __syncthreads();

    // classifier projection: z3 = c3@Wc.T + bc, y3 = aj3@Wc.T
    if (t < 128) {
        int q = t & 63;
        int nd = q >> 2, c = q & 3;
        int i = base + nd;
        if (i < n) {
            const float* src = (t < 64) ? c3s[nd] : aj3s[nd];
            float acc = (t < 64) ? bcs[c] : 0.f;
#pragma unroll 8
            for (int o = 0; o < 32; o++) acc += src[o] * wcs[c * 32 + o];
            if (t < 64) g_z3[i * 4 + c] = acc;
            else        g_y3[i * 4 + c] = acc;
        }
    }
}

// ---------------- layer3 agg in logit space + log_softmax ----------------
__global__ void k_l3f(float* __restrict__ out, int n) {
    int i = blockIdx.x * blockDim.x + threadIdx.x;
    if (i >= n) return;
    const float4* y = (const float4*)g_y3;
    float4 l = ((const float4*)g_z3)[i];
    float4 A = make_float4(0.f, 0.f, 0.f, 0.f), B = A, C = A, D = A;
    int beg = g_off[i], end = g_off[i + 1];
    int j = beg;
    for (; j + 4 <= end; j += 4) {
        int s0 = g_csr[j], s1 = g_csr[j + 1], s2 = g_csr[j + 2], s3 = g_csr[j + 3];
        float4 v0 = y[s0], v1 = y[s1], v2 = y[s2], v3 = y[s3];
        A.x += v0.x; A.y += v0.y; A.z += v0.z; A.w += v0.w;
        B.x += v1.x; B.y += v1.y; B.z += v1.z; B.w += v1.w;
        C.x += v2.x; C.y += v2.y; C.z += v2.z; C.w += v2.w;
        D.x += v3.x; D.y += v3.y; D.z += v3.z; D.w += v3.w;
    }
    for (; j < end; j++) {
        float4 v = y[g_csr[j]];
        A.x += v.x; A.y += v.y; A.z += v.z; A.w += v.w;
    }
    l.x += A.x + B.x + C.x + D.x;
    l.y += A.y + B.y + C.y + D.y;
    l.z += A.z + B.z + C.z + D.z;
    l.w += A.w + B.w + C.w + D.w;

    float mx = fmaxf(fmaxf(l.x, l.y), fmaxf(l.z, l.w));
    float se = expf(l.x - mx) + expf(l.y - mx) + expf(l.z - mx) + expf(l.w - mx);
    float lse = mx + logf(se);
    ((float4*)out)[i] = make_float4(l.x - lse, l.y - lse, l.z - lse, l.w - lse);
}

extern "C" void kernel_launch(void* const* d_in, const int* in_sizes, int n_in,
                              void* d_out, int out_size) {
    const float* x  = (const float*)d_in[0];
    const int*   ei = (const int*)d_in[1];
    const float* ea = (const float*)d_in[2];
    const float* W1 = (const float*)d_in[3];
    const float* b1 = (const float*)d_in[4];
    const float* W2 = (const float*)d_in[5];
    const float* b2 = (const float*)d_in[6];
    const float* W3 = (const float*)d_in[7];
    const float* b3 = (const float*)d_in[8];
    const float* Wc = (const float*)d_in[9];
    const float* bc = (const float*)d_in[10];
    float* out = (float*)d_out;
    int n = in_sizes[0] / 3;
    int e = in_sizes[1] / 2;
    int nb = (n + 511) / 512;
    int half = (e + 1) / 2;

    k_prep<<<(22272 + n + 255) / 256, 256>>>(W1, b1, W2, b2, W3, b3, n);
    k_count<<<(half + 255) / 256, 256>>>(ei, e, half);
    k_scanall<<<nb, 512>>>(n);
    k_fill<<<(half + 255) / 256, 256>>>(ei, ea, e, half);
    k_agg1<<<(n + 255) / 256, 256>>>(x, n);
    k_l12<<<(n + 7) / 8, 128>>>(x, n);
    k_l23<<<(n + 15) / 16, 256>>>(Wc, bc, n);
    k_l3f<<<(n + 255) / 256, 256>>>(out, n);
}